// round 1
// baseline (speedup 1.0000x reference)
#include <cuda_runtime.h>
#include <math.h>

#define NE 8
#define NK 2
#define DDIM 1024
#define IDIM 4096
#define NTOK 8192
#define NROWS (NTOK*NK)
#define OUT_ELEMS (NTOK*DDIM)

// ---- scratch (static device memory; no allocations) ----
__device__ int   g_cnt[NE];
__device__ int   g_list[NE*NTOK];
__device__ float g_rw[NROWS];
__device__ float g_pp[1024*NE];
__device__ float g_h[67108864];   // NROWS * IDIM  (256 MB)
__device__ float g_y[16777216];   // NROWS * DDIM  (64 MB)

// ---- zero per-launch counters ----
__global__ void zero_kernel() {
    if (threadIdx.x < NE) g_cnt[threadIdx.x] = 0;
}

// ---- router: warp per token ----
__global__ void __launch_bounds__(256) router_kernel(const float* __restrict__ x,
                                                     const float* __restrict__ wgate) {
    __shared__ float sw[NE*DDIM];      // 32 KB
    __shared__ float sprob[8][NE];
    int tid = threadIdx.x;
    for (int i = tid; i < NE*DDIM; i += 256) sw[i] = wgate[i];
    __syncthreads();

    int warp = tid >> 5, lane = tid & 31;
    int n = blockIdx.x * 8 + warp;
    const float* xr = x + (size_t)n * DDIM;

    float xv[32];
#pragma unroll
    for (int i = 0; i < 32; i++) xv[i] = xr[i*32 + lane];

    float p[NE];
    float mx = -1e30f;
#pragma unroll
    for (int e = 0; e < NE; e++) {
        float acc = 0.f;
        const float* swe = sw + e*DDIM;
#pragma unroll
        for (int i = 0; i < 32; i++) acc += xv[i] * swe[i*32 + lane];
#pragma unroll
        for (int o = 16; o > 0; o >>= 1) acc += __shfl_xor_sync(0xffffffffu, acc, o);
        p[e] = acc;
        mx = fmaxf(mx, acc);
    }
    float se = 0.f;
#pragma unroll
    for (int e = 0; e < NE; e++) { p[e] = expf(p[e] - mx); se += p[e]; }
    float inv = 1.f / se;
#pragma unroll
    for (int e = 0; e < NE; e++) p[e] *= inv;

    // top-2, lowest index wins ties (matches jax.lax.top_k)
    int e0 = 0;
#pragma unroll
    for (int e = 1; e < NE; e++) if (p[e] > p[e0]) e0 = e;
    int e1 = (e0 == 0) ? 1 : 0;
#pragma unroll
    for (int e = 0; e < NE; e++) if (e != e0 && e != e1 && p[e] > p[e1]) e1 = e;

    if (lane == 0) {
        float w0 = p[e0], w1 = p[e1];
        float s = w0 + w1;
        g_rw[n*2]     = w0 / s;
        g_rw[n*2 + 1] = w1 / s;
        int p0 = atomicAdd(&g_cnt[e0], 1);
        g_list[e0*NTOK + p0] = n*2;
        int p1 = atomicAdd(&g_cnt[e1], 1);
        g_list[e1*NTOK + p1] = n*2 + 1;
#pragma unroll
        for (int e = 0; e < NE; e++) sprob[warp][e] = p[e];
    }
    __syncthreads();
    if (tid == 0) {
#pragma unroll
        for (int e = 0; e < NE; e++) {
            float s = 0.f;
            for (int w = 0; w < 8; w++) s += sprob[w][e];
            g_pp[blockIdx.x*NE + e] = s;
        }
    }
}

// ---- GEMM1: h = silu(Xe @ wg) * (Xe @ wu), 64x64x16 tiles, dual B ----
__global__ void __launch_bounds__(256) gemm1_kernel(const float* __restrict__ x,
                                                    const float* __restrict__ wg,
                                                    const float* __restrict__ wu) {
    int e = blockIdx.z;
    int cnt = g_cnt[e];
    int m0 = blockIdx.x * 64;
    if (m0 >= cnt) return;
    int n0 = blockIdx.y * 64;

    __shared__ float As[16][64];
    __shared__ float Bgs[16][64];
    __shared__ float Bus[16][64];
    __shared__ int rows[64];

    int tid = threadIdx.x;
    if (tid < 64) {
        int pidx = m0 + tid;
        rows[tid] = (pidx < cnt) ? g_list[e*NTOK + pidx] : -1;
    }
    __syncthreads();

    int am = tid >> 2, ak = (tid & 3) << 2;   // A load: row am, k ak..ak+3
    int bk = tid >> 4, bn = (tid & 15) << 2;  // B load: row bk, col bn..bn+3
    int ra = rows[am];
    const float* aRow = (ra >= 0) ? (x + (size_t)(ra >> 1) * DDIM + ak) : nullptr;
    const float* bgp = wg + (size_t)e * DDIM * IDIM + (size_t)bk * IDIM + n0 + bn;
    const float* bup = wu + (size_t)e * DDIM * IDIM + (size_t)bk * IDIM + n0 + bn;

    int tx = tid & 15, ty = tid >> 4;
    float accg[4][4] = {}, accu[4][4] = {};

    for (int k0 = 0; k0 < DDIM; k0 += 16) {
        float4 av = aRow ? *(const float4*)(aRow + k0) : make_float4(0,0,0,0);
        float4 bgv = *(const float4*)(bgp + (size_t)k0 * IDIM);
        float4 buv = *(const float4*)(bup + (size_t)k0 * IDIM);
        __syncthreads();
        As[ak+0][am] = av.x; As[ak+1][am] = av.y; As[ak+2][am] = av.z; As[ak+3][am] = av.w;
        *(float4*)&Bgs[bk][bn] = bgv;
        *(float4*)&Bus[bk][bn] = buv;
        __syncthreads();
#pragma unroll
        for (int kk = 0; kk < 16; kk++) {
            float4 a  = *(const float4*)&As[kk][ty << 2];
            float4 bg = *(const float4*)&Bgs[kk][tx << 2];
            float4 bu = *(const float4*)&Bus[kk][tx << 2];
            float aa[4]  = {a.x, a.y, a.z, a.w};
            float bgv2[4] = {bg.x, bg.y, bg.z, bg.w};
            float buv2[4] = {bu.x, bu.y, bu.z, bu.w};
#pragma unroll
            for (int i = 0; i < 4; i++)
#pragma unroll
                for (int j = 0; j < 4; j++) {
                    accg[i][j] += aa[i] * bgv2[j];
                    accu[i][j] += aa[i] * buv2[j];
                }
        }
    }

#pragma unroll
    for (int i = 0; i < 4; i++) {
        int m = (ty << 2) + i;
        int rid = rows[m];
        if (rid < 0) continue;
        float vals[4];
#pragma unroll
        for (int j = 0; j < 4; j++) {
            float g = accg[i][j];
            float s = g / (1.f + expf(-g));
            vals[j] = s * accu[i][j];
        }
        float* hp = g_h + (size_t)rid * IDIM + n0 + (tx << 2);
        *(float4*)hp = make_float4(vals[0], vals[1], vals[2], vals[3]);
    }
}

// ---- GEMM2: y = (h @ wd) * route_weight, 128x64x16 tiles ----
__global__ void __launch_bounds__(256) gemm2_kernel(const float* __restrict__ wd) {
    int e = blockIdx.z;
    int cnt = g_cnt[e];
    int m0 = blockIdx.x * 128;
    if (m0 >= cnt) return;
    int n0 = blockIdx.y * 64;

    __shared__ float As[16][128];
    __shared__ float Bs[16][64];
    __shared__ int rows[128];

    int tid = threadIdx.x;
    if (tid < 128) {
        int pidx = m0 + tid;
        rows[tid] = (pidx < cnt) ? g_list[e*NTOK + pidx] : -1;
    }
    __syncthreads();

    int am = tid >> 1, ak = (tid & 1) << 3;   // A load: row am, k ak..ak+7
    int bk = tid >> 4, bn = (tid & 15) << 2;
    int ra = rows[am];
    const float* aRow = (ra >= 0) ? (g_h + (size_t)ra * IDIM + ak) : nullptr;
    const float* bp = wd + (size_t)e * IDIM * DDIM + (size_t)bk * DDIM + n0 + bn;

    int tx = tid & 15, ty = tid >> 4;
    float acc[8][4] = {};

    for (int k0 = 0; k0 < IDIM; k0 += 16) {
        float4 av0 = aRow ? *(const float4*)(aRow + k0)     : make_float4(0,0,0,0);
        float4 av1 = aRow ? *(const float4*)(aRow + k0 + 4) : make_float4(0,0,0,0);
        float4 bv  = *(const float4*)(bp + (size_t)k0 * DDIM);
        __syncthreads();
        As[ak+0][am] = av0.x; As[ak+1][am] = av0.y; As[ak+2][am] = av0.z; As[ak+3][am] = av0.w;
        As[ak+4][am] = av1.x; As[ak+5][am] = av1.y; As[ak+6][am] = av1.z; As[ak+7][am] = av1.w;
        *(float4*)&Bs[bk][bn] = bv;
        __syncthreads();
#pragma unroll
        for (int kk = 0; kk < 16; kk++) {
            float4 a0 = *(const float4*)&As[kk][ty << 3];
            float4 a1 = *(const float4*)&As[kk][(ty << 3) + 4];
            float4 b  = *(const float4*)&Bs[kk][tx << 2];
            float aa[8] = {a0.x, a0.y, a0.z, a0.w, a1.x, a1.y, a1.z, a1.w};
            float bb[4] = {b.x, b.y, b.z, b.w};
#pragma unroll
            for (int i = 0; i < 8; i++)
#pragma unroll
                for (int j = 0; j < 4; j++)
                    acc[i][j] += aa[i] * bb[j];
        }
    }

#pragma unroll
    for (int i = 0; i < 8; i++) {
        int m = (ty << 3) + i;
        int rid = rows[m];
        if (rid < 0) continue;
        float w = g_rw[rid];
        float* yp = g_y + (size_t)rid * DDIM + n0 + (tx << 2);
        *(float4*)yp = make_float4(acc[i][0]*w, acc[i][1]*w, acc[i][2]*w, acc[i][3]*w);
    }
}

// ---- combine: out[n] = y[2n] + y[2n+1]  (float4) ----
__global__ void __launch_bounds__(256) combine_kernel(float* __restrict__ out) {
    size_t idx = (size_t)blockIdx.x * 256 + threadIdx.x;     // float4 index, < 2097152
    size_t n   = idx >> 8;                                   // DDIM/4 = 256 float4 per row
    size_t off = idx & 255;
    const float4* y4 = (const float4*)g_y;
    float4 a = y4[(n*2)     * 256 + off];
    float4 b = y4[(n*2 + 1) * 256 + off];
    ((float4*)out)[idx] = make_float4(a.x+b.x, a.y+b.y, a.z+b.z, a.w+b.w);
}

// ---- aux loss (fixed-order deterministic reduction) ----
__global__ void finalize_kernel(float* __restrict__ out, int has_aux) {
    __shared__ float fp[NE];
    int t = threadIdx.x;
    if (t < NE) {
        float s = 0.f;
        for (int b = 0; b < 1024; b++) s += g_pp[b*NE + t];
        float pmean = s / (float)NTOK;
        float f = (float)g_cnt[t] / (float)NROWS;
        fp[t] = f * pmean;
    }
    __syncthreads();
    if (t == 0 && has_aux) {
        float a = 0.f;
        for (int e = 0; e < NE; e++) a += fp[e];
        out[OUT_ELEMS] = 0.02f * (float)NE * a;
    }
}

extern "C" void kernel_launch(void* const* d_in, const int* in_sizes, int n_in,
                              void* d_out, int out_size) {
    const float* x     = (const float*)d_in[0];
    const float* wgate = (const float*)d_in[1];
    const float* wg    = (const float*)d_in[2];
    const float* wu    = (const float*)d_in[3];
    const float* wd    = (const float*)d_in[4];
    float* out = (float*)d_out;

    zero_kernel<<<1, 32>>>();
    router_kernel<<<1024, 256>>>(x, wgate);
    gemm1_kernel<<<dim3(128, 64, 8), 256>>>(x, wg, wu);
    gemm2_kernel<<<dim3(64, 16, 8), 256>>>(wd);
    combine_kernel<<<8192, 256>>>(out);
    finalize_kernel<<<1, 32>>>(out, out_size > OUT_ELEMS ? 1 : 0);
}

// round 3
// speedup vs baseline: 2.0125x; 2.0125x over previous
#include <cuda_runtime.h>
#include <math.h>
#include <stdint.h>

#define NE 8
#define DDIM 1024
#define IDIM 4096
#define NTOK 8192
#define NROWS (NTOK*2)
#define OUT_ELEMS (NTOK*DDIM)

// ---------------- scratch ----------------
__device__ int   g_cnt[NE];
__device__ int   g_list[NE*NTOK];
__device__ float g_rw[NROWS];
__device__ float g_pp[1024*NE];
__device__ float g_h[NROWS*IDIM];   // 256 MB
__device__ float g_y[NROWS*DDIM];   // 64 MB

// ---------------- helpers ----------------
__device__ __forceinline__ uint32_t totf(float f) {
    uint32_t r;
    asm("cvt.rna.tf32.f32 %0, %1;" : "=r"(r) : "f"(f));
    return r;
}
__device__ __forceinline__ void mma8(float* c, const uint32_t* a, uint32_t b0, uint32_t b1) {
    asm volatile(
        "mma.sync.aligned.m16n8k8.row.col.f32.tf32.tf32.f32 "
        "{%0,%1,%2,%3}, {%4,%5,%6,%7}, {%8,%9}, {%0,%1,%2,%3};"
        : "+f"(c[0]), "+f"(c[1]), "+f"(c[2]), "+f"(c[3])
        : "r"(a[0]), "r"(a[1]), "r"(a[2]), "r"(a[3]), "r"(b0), "r"(b1));
}

// fragment-order smem indices (float/u32 units)
// A tile 128x32: slot (i*4+s) stride 33 float4
__device__ __forceinline__ int a_sts_idx(int m, int kl) {
    int i = m >> 4, g = m & 7, regm = (m >> 3) & 1;
    int s = kl >> 3, k3 = kl & 3, regk = (kl >> 2) & 1;
    return (((i*4 + s)*33 + (g*4 + k3)) << 2) + regm + (regk << 1);
}
// B tile 32xN: slot (jp*4+s) stride 33 float4; elem = [b0_je, b1_je, b0_jo, b1_jo]
__device__ __forceinline__ int b_sts_idx(int k, int n) {
    int s = k >> 3, k3 = k & 3, regk = (k >> 2) & 1;
    int jp = n >> 4, jodd = (n >> 3) & 1, nin = n & 7;
    return (((jp*4 + s)*33 + (nin*4 + k3)) << 2) + (jodd << 1) + regk;
}

// ---------------- small kernels ----------------
__global__ void zero_kernel() { if (threadIdx.x < NE) g_cnt[threadIdx.x] = 0; }

__global__ void __launch_bounds__(256) router_kernel(const float* __restrict__ x,
                                                     const float* __restrict__ wgate) {
    __shared__ float sw[NE*DDIM];
    __shared__ float sprob[8][NE];
    int tid = threadIdx.x;
    for (int i = tid; i < NE*DDIM; i += 256) sw[i] = wgate[i];
    __syncthreads();
    int warp = tid >> 5, lane = tid & 31;
    int n = blockIdx.x * 8 + warp;
    const float* xr = x + (size_t)n * DDIM;
    float xv[32];
#pragma unroll
    for (int i = 0; i < 32; i++) xv[i] = xr[i*32 + lane];
    float p[NE]; float mx = -1e30f;
#pragma unroll
    for (int e = 0; e < NE; e++) {
        float acc = 0.f;
        const float* swe = sw + e*DDIM;
#pragma unroll
        for (int i = 0; i < 32; i++) acc += xv[i] * swe[i*32 + lane];
#pragma unroll
        for (int o = 16; o > 0; o >>= 1) acc += __shfl_xor_sync(0xffffffffu, acc, o);
        p[e] = acc; mx = fmaxf(mx, acc);
    }
    float se = 0.f;
#pragma unroll
    for (int e = 0; e < NE; e++) { p[e] = expf(p[e] - mx); se += p[e]; }
    float inv = 1.f / se;
#pragma unroll
    for (int e = 0; e < NE; e++) p[e] *= inv;
    int e0 = 0;
#pragma unroll
    for (int e = 1; e < NE; e++) if (p[e] > p[e0]) e0 = e;
    int e1 = (e0 == 0) ? 1 : 0;
#pragma unroll
    for (int e = 0; e < NE; e++) if (e != e0 && e != e1 && p[e] > p[e1]) e1 = e;
    if (lane == 0) {
        float w0 = p[e0], w1 = p[e1], s = w0 + w1;
        g_rw[n*2] = w0 / s; g_rw[n*2+1] = w1 / s;
        int p0 = atomicAdd(&g_cnt[e0], 1); g_list[e0*NTOK + p0] = n*2;
        int p1 = atomicAdd(&g_cnt[e1], 1); g_list[e1*NTOK + p1] = n*2 + 1;
#pragma unroll
        for (int e = 0; e < NE; e++) sprob[warp][e] = p[e];
    }
    __syncthreads();
    if (tid == 0) {
#pragma unroll
        for (int e = 0; e < NE; e++) {
            float s = 0.f;
            for (int w = 0; w < 8; w++) s += sprob[w][e];
            g_pp[blockIdx.x*NE + e] = s;
        }
    }
}

// ---------------- GEMM1: 128x128x32, gate+up fused ----------------
// smem (u32): buf b at b*12672: A@0 (4224), BG@4224 (4224), BU@8448 (4224)
#define G1_BUF 12672
#define G1_BG  4224
#define G1_BU  8448
#define G1_SMEM_BYTES (2*G1_BUF*4)
#define NT1 (DDIM/32)

__global__ void __launch_bounds__(256) gemm1_mma(const float* __restrict__ x,
                                                 const float* __restrict__ wg,
                                                 const float* __restrict__ wu) {
    extern __shared__ uint32_t sm[];
    __shared__ int rows_s[128];

    int e = blockIdx.z;
    int cnt = g_cnt[e];
    int m0 = blockIdx.x * 128;
    if (m0 >= cnt) return;
    int n0 = blockIdx.y * 128;

    int tid = threadIdx.x, wid = tid >> 5, lane = tid & 31;
    if (tid < 128) rows_s[tid] = (m0 + tid < cnt) ? g_list[e*NTOK + m0 + tid] : -1;
    __syncthreads();

    // global load mapping
    int am = tid >> 1, akh = tid & 1;               // A: row am, k-half akh
    int arid = rows_s[am];
    const float* aptr = (arid >= 0) ? (x + (size_t)(arid >> 1) * DDIM + akh*16) : nullptr;
    int bk = tid >> 3, bnb = (tid & 7) << 4;        // B: k-row bk, n-base bnb
    const float* bgp = wg + ((size_t)e * DDIM + bk) * IDIM + n0 + bnb;
    const float* bup = wu + ((size_t)e * DDIM + bk) * IDIM + n0 + bnb;

    // precomputed STS indices (compile-time unrolled parts)
    int aidx[16], bidx[16];
#pragma unroll
    for (int u = 0; u < 4; u++)
#pragma unroll
        for (int jj = 0; jj < 4; jj++) {
            aidx[u*4+jj] = a_sts_idx(am, akh*16 + u*4 + jj);
            bidx[u*4+jj] = b_sts_idx(bk, bnb + u*4 + jj);
        }

    int wm = wid & 1, wn = wid >> 1;
    float cg[4][4][4], cu[4][4][4];
#pragma unroll
    for (int a = 0; a < 4; a++)
#pragma unroll
        for (int b = 0; b < 4; b++)
#pragma unroll
            for (int c = 0; c < 4; c++) { cg[a][b][c] = 0.f; cu[a][b][c] = 0.f; }

    float4 fA[4], fG[4], fU[4];

    // prologue: load kt=0, store to buf 0
#pragma unroll
    for (int u = 0; u < 4; u++) {
        fA[u] = aptr ? *(const float4*)(aptr + u*4) : make_float4(0,0,0,0);
        fG[u] = *(const float4*)(bgp + u*4);
        fU[u] = *(const float4*)(bup + u*4);
    }
#pragma unroll
    for (int u = 0; u < 4; u++) {
        const float* pa = &fA[u].x; const float* pg = &fG[u].x; const float* pu = &fU[u].x;
#pragma unroll
        for (int jj = 0; jj < 4; jj++) {
            sm[aidx[u*4+jj]]        = totf(pa[jj]);
            sm[G1_BG + bidx[u*4+jj]] = totf(pg[jj]);
            sm[G1_BU + bidx[u*4+jj]] = totf(pu[jj]);
        }
    }
    __syncthreads();

    for (int kt = 0; kt < NT1; kt++) {
        int cur = kt & 1;
        bool pf = (kt + 1 < NT1);
        if (pf) {
            int ko = (kt+1) * 32;
#pragma unroll
            for (int u = 0; u < 4; u++) {
                fA[u] = aptr ? *(const float4*)(aptr + ko + u*4) : make_float4(0,0,0,0);
                fG[u] = *(const float4*)(bgp + (size_t)ko * IDIM + u*4);
                fU[u] = *(const float4*)(bup + (size_t)ko * IDIM + u*4);
            }
        }
        const uint32_t* sb = sm + cur * G1_BUF;
#pragma unroll
        for (int s = 0; s < 4; s++) {
            uint4 afr[4];
#pragma unroll
            for (int mi = 0; mi < 4; mi++)
                afr[mi] = *(const uint4*)&sb[(((wm*4+mi)*4 + s)*33 + lane) << 2];
            uint4 bgfr[2], bufr[2];
#pragma unroll
            for (int p = 0; p < 2; p++) {
                int jp = wn*2 + p;
                bgfr[p] = *(const uint4*)&sb[G1_BG + (((jp*4 + s)*33 + lane) << 2)];
                bufr[p] = *(const uint4*)&sb[G1_BU + (((jp*4 + s)*33 + lane) << 2)];
            }
#pragma unroll
            for (int mi = 0; mi < 4; mi++) {
                const uint32_t* av = (const uint32_t*)&afr[mi];
#pragma unroll
                for (int p = 0; p < 2; p++) {
                    const uint32_t* bg = (const uint32_t*)&bgfr[p];
                    const uint32_t* bu = (const uint32_t*)&bufr[p];
                    mma8(cg[mi][p*2+0], av, bg[0], bg[1]);
                    mma8(cg[mi][p*2+1], av, bg[2], bg[3]);
                    mma8(cu[mi][p*2+0], av, bu[0], bu[1]);
                    mma8(cu[mi][p*2+1], av, bu[2], bu[3]);
                }
            }
        }
        if (pf) {
            uint32_t* db = sm + (cur ^ 1) * G1_BUF;
#pragma unroll
            for (int u = 0; u < 4; u++) {
                const float* pa = &fA[u].x; const float* pg = &fG[u].x; const float* pu = &fU[u].x;
#pragma unroll
                for (int jj = 0; jj < 4; jj++) {
                    db[aidx[u*4+jj]]        = totf(pa[jj]);
                    db[G1_BG + bidx[u*4+jj]] = totf(pg[jj]);
                    db[G1_BU + bidx[u*4+jj]] = totf(pu[jj]);
                }
            }
        }
        __syncthreads();
    }

    // epilogue: h = silu(g)*u
    int g = lane >> 2, tig = lane & 3;
#pragma unroll
    for (int mi = 0; mi < 4; mi++) {
#pragma unroll
        for (int rh = 0; rh < 2; rh++) {
            int m = wm*64 + mi*16 + g + rh*8;
            int rid = rows_s[m];
            if (rid < 0) continue;
            float* hp = g_h + (size_t)rid * IDIM + n0 + wn*32 + tig*2;
#pragma unroll
            for (int ni = 0; ni < 4; ni++) {
                float gv0 = cg[mi][ni][rh*2+0], gv1 = cg[mi][ni][rh*2+1];
                float uv0 = cu[mi][ni][rh*2+0], uv1 = cu[mi][ni][rh*2+1];
                float h0 = gv0 / (1.f + expf(-gv0)) * uv0;
                float h1 = gv1 / (1.f + expf(-gv1)) * uv1;
                *(float2*)(hp + ni*8) = make_float2(h0, h1);
            }
        }
    }
}

// ---------------- GEMM2: 128x256x32 ----------------
// smem (u32): buf b at b*12672: A@0 (4224), B@4224 (8448)
#define G2_BUF 12672
#define G2_B   4224
#define G2_SMEM_BYTES (2*G2_BUF*4)
#define NT2 (IDIM/32)

__global__ void __launch_bounds__(256) gemm2_mma(const float* __restrict__ wd) {
    extern __shared__ uint32_t sm[];
    __shared__ int rows_s[128];

    int e = blockIdx.z;
    int cnt = g_cnt[e];
    int m0 = blockIdx.x * 128;
    if (m0 >= cnt) return;
    int n0 = blockIdx.y * 256;

    int tid = threadIdx.x, wid = tid >> 5, lane = tid & 31;
    if (tid < 128) rows_s[tid] = (m0 + tid < cnt) ? g_list[e*NTOK + m0 + tid] : -1;
    __syncthreads();

    int am = tid >> 1, akh = tid & 1;
    int arid = rows_s[am];
    const float* aptr = (arid >= 0) ? (g_h + (size_t)arid * IDIM + akh*16) : nullptr;
    int bk = tid >> 3, bnb = (tid & 7) << 5;        // B: k-row bk, n-base bnb (32 wide)
    const float* bp = wd + ((size_t)e * IDIM + bk) * DDIM + n0 + bnb;

    int aidx[16], bidx[32];
#pragma unroll
    for (int u = 0; u < 4; u++)
#pragma unroll
        for (int jj = 0; jj < 4; jj++)
            aidx[u*4+jj] = a_sts_idx(am, akh*16 + u*4 + jj);
#pragma unroll
    for (int u = 0; u < 8; u++)
#pragma unroll
        for (int jj = 0; jj < 4; jj++)
            bidx[u*4+jj] = b_sts_idx(bk, bnb + u*4 + jj);

    int wm = wid & 1, wn = wid >> 1;
    float cc[4][8][4];
#pragma unroll
    for (int a = 0; a < 4; a++)
#pragma unroll
        for (int b = 0; b < 8; b++)
#pragma unroll
            for (int c = 0; c < 4; c++) cc[a][b][c] = 0.f;

    float4 fA[4], fB[8];

#pragma unroll
    for (int u = 0; u < 4; u++) fA[u] = aptr ? *(const float4*)(aptr + u*4) : make_float4(0,0,0,0);
#pragma unroll
    for (int u = 0; u < 8; u++) fB[u] = *(const float4*)(bp + u*4);
#pragma unroll
    for (int u = 0; u < 4; u++) {
        const float* pa = &fA[u].x;
#pragma unroll
        for (int jj = 0; jj < 4; jj++) sm[aidx[u*4+jj]] = totf(pa[jj]);
    }
#pragma unroll
    for (int u = 0; u < 8; u++) {
        const float* pb = &fB[u].x;
#pragma unroll
        for (int jj = 0; jj < 4; jj++) sm[G2_B + bidx[u*4+jj]] = totf(pb[jj]);
    }
    __syncthreads();

    for (int kt = 0; kt < NT2; kt++) {
        int cur = kt & 1;
        bool pf = (kt + 1 < NT2);
        if (pf) {
            int ko = (kt+1) * 32;
#pragma unroll
            for (int u = 0; u < 4; u++)
                fA[u] = aptr ? *(const float4*)(aptr + ko + u*4) : make_float4(0,0,0,0);
#pragma unroll
            for (int u = 0; u < 8; u++)
                fB[u] = *(const float4*)(bp + (size_t)ko * DDIM + u*4);
        }
        const uint32_t* sb = sm + cur * G2_BUF;
#pragma unroll
        for (int s = 0; s < 4; s++) {
            uint4 afr[4];
#pragma unroll
            for (int mi = 0; mi < 4; mi++)
                afr[mi] = *(const uint4*)&sb[(((wm*4+mi)*4 + s)*33 + lane) << 2];
            uint4 bfr[4];
#pragma unroll
            for (int p = 0; p < 4; p++) {
                int jp = wn*4 + p;
                bfr[p] = *(const uint4*)&sb[G2_B + (((jp*4 + s)*33 + lane) << 2)];
            }
#pragma unroll
            for (int mi = 0; mi < 4; mi++) {
                const uint32_t* av = (const uint32_t*)&afr[mi];
#pragma unroll
                for (int p = 0; p < 4; p++) {
                    const uint32_t* bb = (const uint32_t*)&bfr[p];
                    mma8(cc[mi][p*2+0], av, bb[0], bb[1]);
                    mma8(cc[mi][p*2+1], av, bb[2], bb[3]);
                }
            }
        }
        if (pf) {
            uint32_t* db = sm + (cur ^ 1) * G2_BUF;
#pragma unroll
            for (int u = 0; u < 4; u++) {
                const float* pa = &fA[u].x;
#pragma unroll
                for (int jj = 0; jj < 4; jj++) db[aidx[u*4+jj]] = totf(pa[jj]);
            }
#pragma unroll
            for (int u = 0; u < 8; u++) {
                const float* pb = &fB[u].x;
#pragma unroll
                for (int jj = 0; jj < 4; jj++) db[G2_B + bidx[u*4+jj]] = totf(pb[jj]);
            }
        }
        __syncthreads();
    }

    int g = lane >> 2, tig = lane & 3;
#pragma unroll
    for (int mi = 0; mi < 4; mi++) {
#pragma unroll
        for (int rh = 0; rh < 2; rh++) {
            int m = wm*64 + mi*16 + g + rh*8;
            int rid = rows_s[m];
            if (rid < 0) continue;
            float w = g_rw[rid];
            float* yp = g_y + (size_t)rid * DDIM + n0 + wn*64 + tig*2;
#pragma unroll
            for (int ni = 0; ni < 8; ni++) {
                float v0 = cc[mi][ni][rh*2+0] * w;
                float v1 = cc[mi][ni][rh*2+1] * w;
                *(float2*)(yp + ni*8) = make_float2(v0, v1);
            }
        }
    }
}

// ---------------- combine + aux ----------------
__global__ void __launch_bounds__(256) combine_kernel(float* __restrict__ out) {
    size_t idx = (size_t)blockIdx.x * 256 + threadIdx.x;
    size_t n = idx >> 8, off = idx & 255;
    const float4* y4 = (const float4*)g_y;
    float4 a = y4[(n*2)     * 256 + off];
    float4 b = y4[(n*2 + 1) * 256 + off];
    ((float4*)out)[idx] = make_float4(a.x+b.x, a.y+b.y, a.z+b.z, a.w+b.w);
}

__global__ void finalize_kernel(float* __restrict__ out, int has_aux) {
    __shared__ float fp[NE];
    int t = threadIdx.x;
    if (t < NE) {
        float s = 0.f;
        for (int b = 0; b < 1024; b++) s += g_pp[b*NE + t];
        float pmean = s / (float)NTOK;
        float f = (float)g_cnt[t] / (float)NROWS;
        fp[t] = f * pmean;
    }
    __syncthreads();
    if (t == 0 && has_aux) {
        float a = 0.f;
        for (int e = 0; e < NE; e++) a += fp[e];
        out[OUT_ELEMS] = 0.02f * (float)NE * a;
    }
}

extern "C" void kernel_launch(void* const* d_in, const int* in_sizes, int n_in,
                              void* d_out, int out_size) {
    const float* x     = (const float*)d_in[0];
    const float* wgate = (const float*)d_in[1];
    const float* wg    = (const float*)d_in[2];
    const float* wu    = (const float*)d_in[3];
    const float* wd    = (const float*)d_in[4];
    float* out = (float*)d_out;

    cudaFuncSetAttribute(gemm1_mma, cudaFuncAttributeMaxDynamicSharedMemorySize, G1_SMEM_BYTES);
    cudaFuncSetAttribute(gemm2_mma, cudaFuncAttributeMaxDynamicSharedMemorySize, G2_SMEM_BYTES);

    zero_kernel<<<1, 32>>>();
    router_kernel<<<1024, 256>>>(x, wgate);
    gemm1_mma<<<dim3(64, 32, 8), 256, G1_SMEM_BYTES>>>(x, wg, wu);
    gemm2_mma<<<dim3(64, 4, 8), 256, G2_SMEM_BYTES>>>(wd);
    combine_kernel<<<8192, 256>>>(out);
    finalize_kernel<<<1, 32>>>(out, out_size > OUT_ELEMS ? 1 : 0);
}

// round 4
// speedup vs baseline: 2.8084x; 1.3955x over previous
#include <cuda_runtime.h>
#include <math.h>
#include <stdint.h>

#define NE 8
#define DDIM 1024
#define IDIM 4096
#define NTOK 8192
#define NROWS (NTOK*2)
#define OUT_ELEMS (NTOK*DDIM)

// ---------------- scratch ----------------
__device__ int   g_cnt[NE];
__device__ int   g_list[NE*NTOK];
__device__ float g_rw[NROWS];
__device__ float g_pp[1024*NE];
__device__ float g_h[NROWS*IDIM];   // 256 MB
__device__ float g_y[NROWS*DDIM];   // 64 MB

// ---------------- helpers ----------------
__device__ __forceinline__ uint32_t totf(float f) {
    uint32_t r;
    asm("cvt.rna.tf32.f32 %0, %1;" : "=r"(r) : "f"(f));
    return r;
}
__device__ __forceinline__ uint4 totf4(float4 v) {
    return make_uint4(totf(v.x), totf(v.y), totf(v.z), totf(v.w));
}
__device__ __forceinline__ void mma8(float* c, const uint32_t* a, uint32_t b0, uint32_t b1) {
    asm volatile(
        "mma.sync.aligned.m16n8k8.row.col.f32.tf32.tf32.f32 "
        "{%0,%1,%2,%3}, {%4,%5,%6,%7}, {%8,%9}, {%0,%1,%2,%3};"
        : "+f"(c[0]), "+f"(c[1]), "+f"(c[2]), "+f"(c[3])
        : "r"(a[0]), "r"(a[1]), "r"(a[2]), "r"(a[3]), "r"(b0), "r"(b1));
}
__device__ __forceinline__ uint32_t f2u(float f) { return __float_as_uint(f); }

// ---------------- small kernels ----------------
__global__ void zero_kernel() { if (threadIdx.x < NE) g_cnt[threadIdx.x] = 0; }

__global__ void __launch_bounds__(256) router_kernel(const float* __restrict__ x,
                                                     const float* __restrict__ wgate) {
    __shared__ float sw[NE*DDIM];
    __shared__ float sprob[8][NE];
    int tid = threadIdx.x;
    for (int i = tid; i < NE*DDIM; i += 256) sw[i] = wgate[i];
    __syncthreads();
    int warp = tid >> 5, lane = tid & 31;
    int n = blockIdx.x * 8 + warp;
    const float* xr = x + (size_t)n * DDIM;
    float xv[32];
#pragma unroll
    for (int i = 0; i < 32; i++) xv[i] = xr[i*32 + lane];
    float p[NE]; float mx = -1e30f;
#pragma unroll
    for (int e = 0; e < NE; e++) {
        float acc = 0.f;
        const float* swe = sw + e*DDIM;
#pragma unroll
        for (int i = 0; i < 32; i++) acc += xv[i] * swe[i*32 + lane];
#pragma unroll
        for (int o = 16; o > 0; o >>= 1) acc += __shfl_xor_sync(0xffffffffu, acc, o);
        p[e] = acc; mx = fmaxf(mx, acc);
    }
    float se = 0.f;
#pragma unroll
    for (int e = 0; e < NE; e++) { p[e] = expf(p[e] - mx); se += p[e]; }
    float inv = 1.f / se;
#pragma unroll
    for (int e = 0; e < NE; e++) p[e] *= inv;
    int e0 = 0;
#pragma unroll
    for (int e = 1; e < NE; e++) if (p[e] > p[e0]) e0 = e;
    int e1 = (e0 == 0) ? 1 : 0;
#pragma unroll
    for (int e = 0; e < NE; e++) if (e != e0 && e != e1 && p[e] > p[e1]) e1 = e;
    if (lane == 0) {
        float w0 = p[e0], w1 = p[e1], s = w0 + w1;
        g_rw[n*2] = w0 / s; g_rw[n*2+1] = w1 / s;
        int p0 = atomicAdd(&g_cnt[e0], 1); g_list[e0*NTOK + p0] = n*2;
        int p1 = atomicAdd(&g_cnt[e1], 1); g_list[e1*NTOK + p1] = n*2 + 1;
#pragma unroll
        for (int e = 0; e < NE; e++) sprob[warp][e] = p[e];
    }
    __syncthreads();
    if (tid == 0) {
#pragma unroll
        for (int e = 0; e < NE; e++) {
            float s = 0.f;
            for (int w = 0; w < 8; w++) s += sprob[w][e];
            g_pp[blockIdx.x*NE + e] = s;
        }
    }
}

// ---------------- GEMM tiles: natural padded layout ----------------
// A tile: 128 rows x 32 k, row stride 36 floats (144B) -> LDS banks {4g+tig} conflict-free
// B tile: 32 k-rows x N cols, row stride N+8 floats    -> LDS banks {8tig+g} conflict-free
#define A_ST   36
#define A_FL   (128*A_ST)            // 4608 floats

#define B1_ST  136                   // 128 + 8
#define B1_FL  (32*B1_ST)            // 4352 floats
#define ST1_FL (A_FL + 2*B1_FL)      // 13312 floats per stage
#define G1_SMEM (2*ST1_FL*4)         // 106496 B

#define B2_ST  264                   // 256 + 8
#define B2_FL  (32*B2_ST)            // 8448 floats
#define ST2_FL (A_FL + B2_FL)        // 13056 floats per stage
#define G2_SMEM (2*ST2_FL*4)         // 104448 B

// ---------------- GEMM1: 128x(128 gate +128 up)x32 ----------------
__global__ void __launch_bounds__(256) gemm1_mma(const float* __restrict__ x,
                                                 const float* __restrict__ wg,
                                                 const float* __restrict__ wu) {
    extern __shared__ float smf[];
    __shared__ int rows_s[128];

    int e = blockIdx.z;
    int cnt = g_cnt[e];
    int m0 = blockIdx.x * 128;
    if (m0 >= cnt) return;
    int n0 = blockIdx.y * 128;

    int tid = threadIdx.x, wid = tid >> 5, lane = tid & 31;
    if (tid < 128) rows_s[tid] = (m0 + tid < cnt) ? g_list[e*NTOK + m0 + tid] : -1;
    __syncthreads();

    // loader mapping
    int ar = tid >> 1;                    // A row 0..127
    int ac0 = (tid & 1) * 16;             // A float base (2 half-rows of 16 floats)
    int arid = rows_s[ar];
    const float* aptr = (arid >= 0) ? (x + (size_t)(arid >> 1) * DDIM) : nullptr;
    int bk = tid >> 3;                    // B k-row 0..31
    int bn = tid & 7;                     // B chunk lane
    const float* bgp = wg + ((size_t)e * DDIM + bk) * IDIM + n0;
    const float* bup = wu + ((size_t)e * DDIM + bk) * IDIM + n0;

    int wm = wid & 1, wn = wid >> 1;
    int g = lane >> 2, tig = lane & 3;

    float cg[4][4][4], cu[4][4][4];
#pragma unroll
    for (int a = 0; a < 4; a++)
#pragma unroll
        for (int b = 0; b < 4; b++)
#pragma unroll
            for (int c = 0; c < 4; c++) { cg[a][b][c] = 0.f; cu[a][b][c] = 0.f; }

    float4 fA[4], fG[4], fU[4];

#define LOADG1(KT) do {                                                          \
    int kf = (KT) * 32;                                                          \
    _Pragma("unroll")                                                            \
    for (int i = 0; i < 4; i++)                                                  \
        fA[i] = aptr ? *(const float4*)(aptr + kf + ac0 + i*4)                   \
                     : make_float4(0,0,0,0);                                     \
    _Pragma("unroll")                                                            \
    for (int i = 0; i < 4; i++) {                                                \
        fG[i] = *(const float4*)(bgp + (size_t)kf * IDIM + i*32 + bn*4);         \
        fU[i] = *(const float4*)(bup + (size_t)kf * IDIM + i*32 + bn*4);         \
    }                                                                            \
} while (0)

#define STORE1(SB) do {                                                          \
    float* sb_ = (SB);                                                           \
    _Pragma("unroll")                                                            \
    for (int i = 0; i < 4; i++)                                                  \
        *(uint4*)(sb_ + ar*A_ST + ac0 + i*4) = totf4(fA[i]);                     \
    _Pragma("unroll")                                                            \
    for (int i = 0; i < 4; i++) {                                                \
        *(uint4*)(sb_ + A_FL + bk*B1_ST + i*32 + bn*4)          = totf4(fG[i]);  \
        *(uint4*)(sb_ + A_FL + B1_FL + bk*B1_ST + i*32 + bn*4)  = totf4(fU[i]);  \
    }                                                                            \
} while (0)

#define COMPUTE1(SB) do {                                                        \
    const float* As_ = (SB);                                                     \
    const float* Bg_ = (SB) + A_FL;                                              \
    const float* Bu_ = (SB) + A_FL + B1_FL;                                      \
    _Pragma("unroll")                                                            \
    for (int s = 0; s < 4; s++) {                                                \
        uint32_t afr[4][4];                                                      \
        _Pragma("unroll")                                                        \
        for (int mi = 0; mi < 4; mi++) {                                         \
            int r = wm*64 + mi*16 + g;                                           \
            int c = s*8 + tig;                                                   \
            afr[mi][0] = f2u(As_[r*A_ST + c]);                                   \
            afr[mi][1] = f2u(As_[(r+8)*A_ST + c]);                               \
            afr[mi][2] = f2u(As_[r*A_ST + c + 4]);                               \
            afr[mi][3] = f2u(As_[(r+8)*A_ST + c + 4]);                           \
        }                                                                        \
        _Pragma("unroll")                                                        \
        for (int p = 0; p < 4; p++) {                                            \
            int col = wn*32 + p*8 + g;                                           \
            uint32_t g0 = f2u(Bg_[(s*8+tig)*B1_ST + col]);                       \
            uint32_t g1 = f2u(Bg_[(s*8+tig+4)*B1_ST + col]);                     \
            uint32_t u0 = f2u(Bu_[(s*8+tig)*B1_ST + col]);                       \
            uint32_t u1 = f2u(Bu_[(s*8+tig+4)*B1_ST + col]);                     \
            _Pragma("unroll")                                                    \
            for (int mi = 0; mi < 4; mi++) {                                     \
                mma8(cg[mi][p], afr[mi], g0, g1);                                \
                mma8(cu[mi][p], afr[mi], u0, u1);                                \
            }                                                                    \
        }                                                                        \
    }                                                                            \
} while (0)

    LOADG1(0);
    STORE1(smf);
    __syncthreads();
    for (int kt = 0; kt < 32; kt++) {
        bool pf = (kt + 1 < 32);
        if (pf) LOADG1(kt + 1);
        COMPUTE1(smf + (kt & 1) * ST1_FL);
        if (pf) STORE1(smf + ((kt + 1) & 1) * ST1_FL);
        __syncthreads();
    }

    // epilogue: h = silu(gate) * up
#pragma unroll
    for (int mi = 0; mi < 4; mi++) {
#pragma unroll
        for (int rh = 0; rh < 2; rh++) {
            int m = wm*64 + mi*16 + g + rh*8;
            int rid = rows_s[m];
            if (rid < 0) continue;
            float* hp = g_h + (size_t)rid * IDIM + n0 + wn*32 + 2*tig;
#pragma unroll
            for (int p = 0; p < 4; p++) {
                float gv0 = cg[mi][p][rh*2+0], gv1 = cg[mi][p][rh*2+1];
                float uv0 = cu[mi][p][rh*2+0], uv1 = cu[mi][p][rh*2+1];
                float h0 = gv0 / (1.f + expf(-gv0)) * uv0;
                float h1 = gv1 / (1.f + expf(-gv1)) * uv1;
                *(float2*)(hp + p*8) = make_float2(h0, h1);
            }
        }
    }
}

// ---------------- GEMM2: 128x256x32, y = (h @ wd) * rw ----------------
__global__ void __launch_bounds__(256) gemm2_mma(const float* __restrict__ wd) {
    extern __shared__ float smf[];
    __shared__ int rows_s[128];

    int e = blockIdx.z;
    int cnt = g_cnt[e];
    int m0 = blockIdx.x * 128;
    if (m0 >= cnt) return;
    int n0 = blockIdx.y * 256;

    int tid = threadIdx.x, wid = tid >> 5, lane = tid & 31;
    if (tid < 128) rows_s[tid] = (m0 + tid < cnt) ? g_list[e*NTOK + m0 + tid] : -1;
    __syncthreads();

    int ar = tid >> 1;
    int ac0 = (tid & 1) * 16;
    int arid = rows_s[ar];
    const float* aptr = (arid >= 0) ? (g_h + (size_t)arid * IDIM) : nullptr;
    int bk = tid >> 3;
    int bn = tid & 7;
    const float* bp = wd + ((size_t)e * IDIM + bk) * DDIM + n0;

    int wm = wid & 1, wn = wid >> 1;
    int g = lane >> 2, tig = lane & 3;

    float cc[4][8][4];
#pragma unroll
    for (int a = 0; a < 4; a++)
#pragma unroll
        for (int b = 0; b < 8; b++)
#pragma unroll
            for (int c = 0; c < 4; c++) cc[a][b][c] = 0.f;

    float4 fA[4], fB[8];

#define LOADG2(KT) do {                                                          \
    int kf = (KT) * 32;                                                          \
    _Pragma("unroll")                                                            \
    for (int i = 0; i < 4; i++)                                                  \
        fA[i] = aptr ? *(const float4*)(aptr + kf + ac0 + i*4)                   \
                     : make_float4(0,0,0,0);                                     \
    _Pragma("unroll")                                                            \
    for (int i = 0; i < 8; i++)                                                  \
        fB[i] = *(const float4*)(bp + (size_t)kf * DDIM + i*32 + bn*4);          \
} while (0)

#define STORE2(SB) do {                                                          \
    float* sb_ = (SB);                                                           \
    _Pragma("unroll")                                                            \
    for (int i = 0; i < 4; i++)                                                  \
        *(uint4*)(sb_ + ar*A_ST + ac0 + i*4) = totf4(fA[i]);                     \
    _Pragma("unroll")                                                            \
    for (int i = 0; i < 8; i++)                                                  \
        *(uint4*)(sb_ + A_FL + bk*B2_ST + i*32 + bn*4) = totf4(fB[i]);           \
} while (0)

#define COMPUTE2(SB) do {                                                        \
    const float* As_ = (SB);                                                     \
    const float* Bs_ = (SB) + A_FL;                                              \
    _Pragma("unroll")                                                            \
    for (int s = 0; s < 4; s++) {                                                \
        uint32_t afr[4][4];                                                      \
        _Pragma("unroll")                                                        \
        for (int mi = 0; mi < 4; mi++) {                                         \
            int r = wm*64 + mi*16 + g;                                           \
            int c = s*8 + tig;                                                   \
            afr[mi][0] = f2u(As_[r*A_ST + c]);                                   \
            afr[mi][1] = f2u(As_[(r+8)*A_ST + c]);                               \
            afr[mi][2] = f2u(As_[r*A_ST + c + 4]);                               \
            afr[mi][3] = f2u(As_[(r+8)*A_ST + c + 4]);                           \
        }                                                                        \
        _Pragma("unroll")                                                        \
        for (int p = 0; p < 8; p++) {                                            \
            int col = wn*64 + p*8 + g;                                           \
            uint32_t b0 = f2u(Bs_[(s*8+tig)*B2_ST + col]);                       \
            uint32_t b1 = f2u(Bs_[(s*8+tig+4)*B2_ST + col]);                     \
            _Pragma("unroll")                                                    \
            for (int mi = 0; mi < 4; mi++)                                       \
                mma8(cc[mi][p], afr[mi], b0, b1);                                \
        }                                                                        \
    }                                                                            \
} while (0)

    LOADG2(0);
    STORE2(smf);
    __syncthreads();
    for (int kt = 0; kt < 128; kt++) {
        bool pf = (kt + 1 < 128);
        if (pf) LOADG2(kt + 1);
        COMPUTE2(smf + (kt & 1) * ST2_FL);
        if (pf) STORE2(smf + ((kt + 1) & 1) * ST2_FL);
        __syncthreads();
    }

#pragma unroll
    for (int mi = 0; mi < 4; mi++) {
#pragma unroll
        for (int rh = 0; rh < 2; rh++) {
            int m = wm*64 + mi*16 + g + rh*8;
            int rid = rows_s[m];
            if (rid < 0) continue;
            float w = g_rw[rid];
            float* yp = g_y + (size_t)rid * DDIM + n0 + wn*64 + 2*tig;
#pragma unroll
            for (int p = 0; p < 8; p++) {
                float v0 = cc[mi][p][rh*2+0] * w;
                float v1 = cc[mi][p][rh*2+1] * w;
                *(float2*)(yp + p*8) = make_float2(v0, v1);
            }
        }
    }
}

// ---------------- combine + aux ----------------
__global__ void __launch_bounds__(256) combine_kernel(float* __restrict__ out) {
    size_t idx = (size_t)blockIdx.x * 256 + threadIdx.x;
    size_t n = idx >> 8, off = idx & 255;
    const float4* y4 = (const float4*)g_y;
    float4 a = y4[(n*2)     * 256 + off];
    float4 b = y4[(n*2 + 1) * 256 + off];
    ((float4*)out)[idx] = make_float4(a.x+b.x, a.y+b.y, a.z+b.z, a.w+b.w);
}

__global__ void finalize_kernel(float* __restrict__ out, int has_aux) {
    __shared__ float fp[NE];
    int t = threadIdx.x;
    if (t < NE) {
        float s = 0.f;
        for (int b = 0; b < 1024; b++) s += g_pp[b*NE + t];
        float pmean = s / (float)NTOK;
        float f = (float)g_cnt[t] / (float)NROWS;
        fp[t] = f * pmean;
    }
    __syncthreads();
    if (t == 0 && has_aux) {
        float a = 0.f;
        for (int e = 0; e < NE; e++) a += fp[e];
        out[OUT_ELEMS] = 0.02f * (float)NE * a;
    }
}

extern "C" void kernel_launch(void* const* d_in, const int* in_sizes, int n_in,
                              void* d_out, int out_size) {
    const float* x     = (const float*)d_in[0];
    const float* wgate = (const float*)d_in[1];
    const float* wg    = (const float*)d_in[2];
    const float* wu    = (const float*)d_in[3];
    const float* wd    = (const float*)d_in[4];
    float* out = (float*)d_out;

    cudaFuncSetAttribute(gemm1_mma, cudaFuncAttributeMaxDynamicSharedMemorySize, G1_SMEM);
    cudaFuncSetAttribute(gemm2_mma, cudaFuncAttributeMaxDynamicSharedMemorySize, G2_SMEM);

    zero_kernel<<<1, 32>>>();
    router_kernel<<<1024, 256>>>(x, wgate);
    gemm1_mma<<<dim3(64, 32, 8), 256, G1_SMEM>>>(x, wg, wu);
    gemm2_mma<<<dim3(64, 4, 8), 256, G2_SMEM>>>(wd);
    combine_kernel<<<8192, 256>>>(out);
    finalize_kernel<<<1, 32>>>(out, out_size > OUT_ELEMS ? 1 : 0);
}